// round 7
// baseline (speedup 1.0000x reference)
#include <cuda_runtime.h>
#include <cuda_bf16.h>
#include <cstdint>

#define BATCH   4
#define SEQ     1024
#define DMODEL  512
#define NHEADS  8
#define DK      64
#define NLAYERS 6
#define DFFN    2048
#define MROWS   (BATCH*SEQ)   // 4096
#define ALSTRIDE ((long long)BATCH*NHEADS*SEQ*SEQ)   // attn layer stride

// ---------------- scratch (device globals) -------------------------------------
__device__ float g_x  [MROWS*DMODEL];     // residual stream (fp32)
__device__ float g_y  [MROWS*DMODEL];     // gemm fp32 out (pre-LN)
__device__ float g_rinv[NLAYERS*BATCH*NHEADS*SEQ];                    // 1/rowsum
__device__ __nv_bfloat16 g_xh[MROWS*DMODEL],  g_xl[MROWS*DMODEL];    // x split
__device__ __nv_bfloat16 g_qh[3*MROWS*DMODEL], g_ql[3*MROWS*DMODEL]; // q|k|v split
__device__ __nv_bfloat16 g_ch[MROWS*DMODEL],  g_cl[MROWS*DMODEL];    // ctx split
__device__ __nv_bfloat16 g_fh[MROWS*DFFN],    g_fl[MROWS*DFFN];      // ffn split

// bf16 split transposed weights Wt[n][k]: qkv(1536x512)|o(512x512)|w1(2048x512)|w2(512x2048)
#define WL_STRIDE 3145728
#define WOFF_QKV  0
#define WOFF_O    786432
#define WOFF_1    1048576
#define WOFF_2    2097152
__device__ __nv_bfloat16 g_whi[NLAYERS*WL_STRIDE];
__device__ __nv_bfloat16 g_wlo[NLAYERS*WL_STRIDE];

// ---------------- helpers -------------------------------------------------------
__device__ __forceinline__ uint32_t smem_u32(const void* p) {
    uint32_t a;
    asm("{ .reg .u64 t; cvta.to.shared.u64 t, %1; cvt.u32.u64 %0, t; }" : "=r"(a) : "l"(p));
    return a;
}
__device__ __forceinline__ void ldm4(uint32_t* r, uint32_t a) {
    asm volatile("ldmatrix.sync.aligned.m8n8.x4.shared.b16 {%0,%1,%2,%3}, [%4];"
        : "=r"(r[0]), "=r"(r[1]), "=r"(r[2]), "=r"(r[3]) : "r"(a));
}
__device__ __forceinline__ void ldm4t(uint32_t* r, uint32_t a) {
    asm volatile("ldmatrix.sync.aligned.m8n8.x4.trans.shared.b16 {%0,%1,%2,%3}, [%4];"
        : "=r"(r[0]), "=r"(r[1]), "=r"(r[2]), "=r"(r[3]) : "r"(a));
}
__device__ __forceinline__ void mma16816(float* d, const uint32_t* a, const uint32_t* b) {
    asm volatile("mma.sync.aligned.m16n8k16.row.col.f32.bf16.bf16.f32 "
        "{%0,%1,%2,%3}, {%4,%5,%6,%7}, {%8,%9}, {%0,%1,%2,%3};"
        : "+f"(d[0]), "+f"(d[1]), "+f"(d[2]), "+f"(d[3])
        : "r"(a[0]), "r"(a[1]), "r"(a[2]), "r"(a[3]), "r"(b[0]), "r"(b[1]));
}
__device__ __forceinline__ void split2(float x, float y, uint32_t& hi, uint32_t& lo) {
    __nv_bfloat162 h = __floats2bfloat162_rn(x, y);
    float hx = __bfloat162float(h.x), hy = __bfloat162float(h.y);
    __nv_bfloat162 l2 = __floats2bfloat162_rn(x - hx, y - hy);
    hi = *(uint32_t*)&h;
    lo = *(uint32_t*)&l2;
}
__device__ __forceinline__ void cpa16(uint32_t dst, const void* src) {
    asm volatile("cp.async.cg.shared.global [%0], [%1], 16;" :: "r"(dst), "l"(src));
}
#define CP_COMMIT() asm volatile("cp.async.commit_group;" ::: "memory")
template<int N> __device__ __forceinline__ void cp_wait() {
    asm volatile("cp.async.wait_group %0;" :: "n"(N) : "memory");
}

// ---------------- embedding + positional encoding (writes x + split) -----------
__global__ void embed_kernel(const int* __restrict__ tok,
                             const float* __restrict__ emb) {
    int p = blockIdx.x * 256 + threadIdx.x;
    if (p >= MROWS*DMODEL/2) return;
    int idx = p * 2;
    int row = idx >> 9;
    int d   = idx & (DMODEL-1);
    int s   = row & (SEQ-1);
    int tk  = tok[row];
    float freq = expf((float)d * (-9.210340371976184f / (float)DMODEL));
    float ang  = (float)s * freq;
    float v0 = emb[tk*DMODEL + d]     + sinf(ang);
    float v1 = emb[tk*DMODEL + d + 1] + cosf(ang);
    *(float2*)&g_x[idx] = make_float2(v0, v1);
    uint32_t h, l; split2(v0, v1, h, l);
    *(uint32_t*)&g_xh[idx] = h;
    *(uint32_t*)&g_xl[idx] = l;
}

// ---------------- weight transpose + split kernels ------------------------------
__global__ void wconv4_kernel(const float* __restrict__ Wq, const float* __restrict__ Wk,
                              const float* __restrict__ Wv, const float* __restrict__ Wo,
                              __nv_bfloat16* __restrict__ hi, __nv_bfloat16* __restrict__ lo) {
    __shared__ float tl[32][33];
    int z = blockIdx.z, lyr = z >> 2, which = z & 3;
    const float* src;
    size_t doff;
    switch (which) {
        case 0: src = Wq; doff = WOFF_QKV;          break;
        case 1: src = Wk; doff = WOFF_QKV + 262144; break;
        case 2: src = Wv; doff = WOFF_QKV + 524288; break;
        default: src = Wo; doff = WOFF_O;           break;
    }
    src += (size_t)lyr * 262144;
    hi  += (size_t)lyr * WL_STRIDE + doff;
    lo  += (size_t)lyr * WL_STRIDE + doff;
    int n0 = blockIdx.x*32, k0 = blockIdx.y*32;
    int tx = threadIdx.x & 31, tg = threadIdx.x >> 5;
    #pragma unroll
    for (int r = tg; r < 32; r += 8)
        tl[r][tx] = src[(size_t)(k0 + r)*512 + n0 + tx];
    __syncthreads();
    #pragma unroll
    for (int r = tg; r < 32; r += 8) {
        float x = tl[tx][r];
        __nv_bfloat16 h = __float2bfloat16(x);
        size_t o = (size_t)(n0 + r)*512 + k0 + tx;
        hi[o] = h;
        lo[o] = __float2bfloat16(x - __bfloat162float(h));
    }
}

__global__ void wconv_kernel(const float* __restrict__ src,
                             __nv_bfloat16* __restrict__ hi,
                             __nv_bfloat16* __restrict__ lo,
                             int K, int N, long srcStride, long dstStride) {
    __shared__ float tl[32][33];
    int l = blockIdx.z;
    src += (size_t)l * srcStride;
    hi  += (size_t)l * dstStride;
    lo  += (size_t)l * dstStride;
    int n0 = blockIdx.x*32, k0 = blockIdx.y*32;
    int tx = threadIdx.x & 31, tg = threadIdx.x >> 5;
    #pragma unroll
    for (int r = tg; r < 32; r += 8)
        tl[r][tx] = src[(size_t)(k0 + r)*N + n0 + tx];
    __syncthreads();
    #pragma unroll
    for (int r = tg; r < 32; r += 8) {
        float x = tl[tx][r];
        __nv_bfloat16 h = __float2bfloat16(x);
        size_t o = (size_t)(n0 + r)*K + k0 + tx;
        hi[o] = h;
        lo[o] = __float2bfloat16(x - __bfloat162float(h));
    }
}

// ---------------- 3-stage pipelined HMMA GEMM: C = A @ Bt^T ---------------------
#define GSTAGE    73728
#define GEMM_SMEM (3*GSTAGE)

__device__ __forceinline__ void gemm_stage_load(
        uint32_t sbase, int t,
        const __nv_bfloat16* Ah, const __nv_bfloat16* Al,
        const __nv_bfloat16* Bh, const __nv_bfloat16* Bl,
        int m0, int n0, int k0, int K) {
    #pragma unroll
    for (int i = 0; i < 4; i++) {
        int seg = i*256 + t;
        int r = seg >> 3, c = seg & 7;
        uint32_t so = (uint32_t)r*144 + c*16;
        size_t ga = (size_t)(m0 + r)*K + k0 + c*8;
        size_t gb = (size_t)(n0 + r)*K + k0 + c*8;
        cpa16(sbase +         so, Ah + ga);
        cpa16(sbase + 18432 + so, Al + ga);
        cpa16(sbase + 36864 + so, Bh + gb);
        cpa16(sbase + 55296 + so, Bl + gb);
    }
}

template<int MODE>
__global__ __launch_bounds__(256) void mma_gemm(
        const __nv_bfloat16* __restrict__ Ah, const __nv_bfloat16* __restrict__ Al,
        const __nv_bfloat16* __restrict__ Bh, const __nv_bfloat16* __restrict__ Bl,
        float* __restrict__ Cf,
        __nv_bfloat16* __restrict__ Ch, __nv_bfloat16* __restrict__ Cl,
        int N, int K) {
    extern __shared__ char sm[];
    const uint32_t sb = smem_u32(sm);
    int t = threadIdx.x, l = t & 31, wid = t >> 5;
    int m0 = blockIdx.y * 128, n0 = blockIdx.x * 128;
    int wm = (wid & 3) * 32, wn = (wid >> 2) * 64;

    float acc[2][8][4];
    #pragma unroll
    for (int i = 0; i < 2; i++)
        #pragma unroll
        for (int j = 0; j < 8; j++)
            #pragma unroll
            for (int q = 0; q < 4; q++) acc[i][j][q] = 0.f;

    const int NK = K >> 6;
    gemm_stage_load(sb, t, Ah, Al, Bh, Bl, m0, n0, 0, K);
    CP_COMMIT();
    if (NK > 1) {
        gemm_stage_load(sb + GSTAGE, t, Ah, Al, Bh, Bl, m0, n0, 64, K);
        CP_COMMIT();
    }

    int s_cur = 0, s_pre = 2;
    for (int kc = 0; kc < NK; kc++) {
        if (kc < NK - 1) cp_wait<1>(); else cp_wait<0>();
        __syncthreads();
        if (kc + 2 < NK) {
            gemm_stage_load(sb + s_pre*GSTAGE, t, Ah, Al, Bh, Bl,
                            m0, n0, (kc+2)*64, K);
            CP_COMMIT();
        }

        const uint32_t SB = sb + s_cur*GSTAGE;
        const uint32_t AH = SB, AL = SB + 18432, BH = SB + 36864, BL = SB + 55296;
        #pragma unroll
        for (int ks = 0; ks < 4; ks++) {
            uint32_t aH[2][4], aL[2][4];
            #pragma unroll
            for (int ra = 0; ra < 2; ra++) {
                uint32_t off = (uint32_t)(wm + ra*16 + (l & 15))*144 + (ks*16 + (l >> 4)*8)*2;
                ldm4(aH[ra], AH + off);
                ldm4(aL[ra], AL + off);
            }
            #pragma unroll
            for (int g = 0; g < 4; g++) {
                uint32_t bH[4], bL[4];
                uint32_t off = (uint32_t)(wn + g*16 + (l & 7) + ((l >> 4) << 3))*144
                             + (ks*16 + ((l >> 3) & 1)*8)*2;
                ldm4(bH, BH + off); ldm4(bL, BL + off);
                mma16816(acc[0][2*g],   aH[0], &bH[0]);
                mma16816(acc[0][2*g+1], aH[0], &bH[2]);
                mma16816(acc[1][2*g],   aH[1], &bH[0]);
                mma16816(acc[1][2*g+1], aH[1], &bH[2]);
                mma16816(acc[0][2*g],   aH[0], &bL[0]);
                mma16816(acc[0][2*g+1], aH[0], &bL[2]);
                mma16816(acc[1][2*g],   aH[1], &bL[0]);
                mma16816(acc[1][2*g+1], aH[1], &bL[2]);
                mma16816(acc[0][2*g],   aL[0], &bH[0]);
                mma16816(acc[0][2*g+1], aL[0], &bH[2]);
                mma16816(acc[1][2*g],   aL[1], &bH[0]);
                mma16816(acc[1][2*g+1], aL[1], &bH[2]);
            }
        }
        s_cur = (s_cur == 2) ? 0 : s_cur + 1;
        s_pre = (s_pre == 2) ? 0 : s_pre + 1;
    }

    #pragma unroll
    for (int ra = 0; ra < 2; ra++)
        #pragma unroll
        for (int na = 0; na < 8; na++) {
            int n = n0 + wn + na*8 + 2*(l & 3);
            #pragma unroll
            for (int half = 0; half < 2; half++) {
                int m = m0 + wm + ra*16 + (l >> 2) + half*8;
                float2 v = make_float2(acc[ra][na][half*2], acc[ra][na][half*2 + 1]);
                if (MODE == 0) {
                    *(float2*)&Cf[(size_t)m*N + n] = v;
                } else {
                    if (MODE == 2) { v.x = fmaxf(v.x, 0.f); v.y = fmaxf(v.y, 0.f); }
                    uint32_t hh, ll; split2(v.x, v.y, hh, ll);
                    size_t off;
                    if (MODE == 1) {
                        int sel = n >> 9, n2 = n & 511;
                        int h = n2 >> 6, dk = n2 & 63;
                        int b = m >> 10, s = m & 1023;
                        off = (size_t)sel*MROWS*DMODEL
                            + ((size_t)((b*NHEADS + h)*SEQ + s))*DK + dk;
                    } else {
                        off = (size_t)m*N + n;
                    }
                    *(uint32_t*)&Ch[off] = hh;
                    *(uint32_t*)&Cl[off] = ll;
                }
            }
        }
}

// ---------------- single-pass HMMA attention, K double-buffered ------------------
// Also normalizes layer-1's attn block (same b,h,qb) as a tail — overlaps the
// normalization bandwidth with other CTAs' HMMA compute.
#define ATTN_SMEM 221184

__global__ __launch_bounds__(256) void attn_kernel(
        const int* __restrict__ tok, float* __restrict__ attn_out,
        float* __restrict__ rinv_g, int layer) {
    extern __shared__ char sm[];
    const uint32_t sb = smem_u32(sm);
    const uint32_t QH = sb,           QL = sb + 18432;
    const uint32_t VH = sb + 110592,  VL = sb + 129024;
    const uint32_t PH = sb + 147456,  PL = sb + 182272;
    char* cPH = sm + 147456;  char* cPL = sm + 182272;
    float* mskS = (float*)(sm + 217088);   // 1024 floats

    int t = threadIdx.x, l = t & 31, wid = t >> 5;
    int qb = blockIdx.x, h = blockIdx.y, b = blockIdx.z;
    int q0 = qb * 128;
    size_t hoff = ((size_t)(b*NHEADS + h)*SEQ)*DK;
    const __nv_bfloat16* qh = g_qh + hoff + (size_t)q0*DK;
    const __nv_bfloat16* ql = g_ql + hoff + (size_t)q0*DK;
    const __nv_bfloat16* kh = g_qh + (size_t)MROWS*DMODEL + hoff;
    const __nv_bfloat16* kl = g_ql + (size_t)MROWS*DMODEL + hoff;
    const __nv_bfloat16* vh = kh + (size_t)MROWS*DMODEL;
    const __nv_bfloat16* vl = kl + (size_t)MROWS*DMODEL;

    for (int j = t; j < SEQ; j += 256)
        mskS[j] = (tok[b*SEQ + j] == 0) ? 1.f : 0.f;
    #pragma unroll
    for (int i = 0; i < 4; i++) {                 // Q + K(0) prologue
        int seg = i*256 + t, r = seg >> 3, c = seg & 7;
        uint32_t so = (uint32_t)r*144 + c*16;
        cpa16(QH + so, qh + (size_t)r*64 + c*8);
        cpa16(QL + so, ql + (size_t)r*64 + c*8);
        cpa16(sb + 36864 + so, kh + (size_t)r*64 + c*8);
        cpa16(sb + 55296 + so, kl + (size_t)r*64 + c*8);
    }
    CP_COMMIT(); cp_wait<0>();
    __syncthreads();

    float rs0 = 0.f, rs1 = 0.f;
    float cacc[8][4];
    #pragma unroll
    for (int j = 0; j < 8; j++)
        #pragma unroll
        for (int q = 0; q < 4; q++) cacc[j][q] = 0.f;

    int r0 = wid*16 + (l >> 2);
    long long abase = ((((long long)layer*BATCH + b)*NHEADS + h)*SEQ + q0)
                      * (long long)SEQ;

    for (int kc = 0; kc < 8; kc++) {
        const uint32_t KHc = sb + 36864 + (uint32_t)(kc & 1)*36864;
        const uint32_t KLc = KHc + 18432;
        #pragma unroll
        for (int i = 0; i < 4; i++) {
            int seg = i*256 + t, r = seg >> 3, c = seg & 7;
            uint32_t so = (uint32_t)r*144 + c*16;
            cpa16(VH + so, vh + (size_t)(kc*128 + r)*64 + c*8);
            cpa16(VL + so, vl + (size_t)(kc*128 + r)*64 + c*8);
        }
        CP_COMMIT();
        if (kc < 7) {
            const uint32_t KHn = sb + 36864 + (uint32_t)((kc+1) & 1)*36864;
            #pragma unroll
            for (int i = 0; i < 4; i++) {
                int seg = i*256 + t, r = seg >> 3, c = seg & 7;
                uint32_t so = (uint32_t)r*144 + c*16;
                cpa16(KHn + so,         kh + (size_t)((kc+1)*128 + r)*64 + c*8);
                cpa16(KHn + 18432 + so, kl + (size_t)((kc+1)*128 + r)*64 + c*8);
            }
            CP_COMMIT();
        }

        // ---- QK on resident K(kc) ----
        float sacc[16][4];
        #pragma unroll
        for (int j = 0; j < 16; j++)
            #pragma unroll
            for (int q = 0; q < 4; q++) sacc[j][q] = 0.f;

        #pragma unroll
        for (int ks = 0; ks < 4; ks++) {
            uint32_t aH[4], aL[4];
            uint32_t aoff = (uint32_t)(wid*16 + (l & 15))*144 + (ks*16 + (l >> 4)*8)*2;
            ldm4(aH, QH + aoff); ldm4(aL, QL + aoff);
            #pragma unroll
            for (int gp = 0; gp < 4; gp++) {
                int g0 = 2*gp, g1 = g0 + 1;
                uint32_t b0H[4], b0L[4], b1H[4], b1L[4];
                uint32_t bo0 = (uint32_t)(g0*16 + (l & 7) + ((l >> 4) << 3))*144
                             + (ks*16 + ((l >> 3) & 1)*8)*2;
                uint32_t bo1 = (uint32_t)(g1*16 + (l & 7) + ((l >> 4) << 3))*144
                             + (ks*16 + ((l >> 3) & 1)*8)*2;
                ldm4(b0H, KHc + bo0); ldm4(b0L, KLc + bo0);
                ldm4(b1H, KHc + bo1); ldm4(b1L, KLc + bo1);
                mma16816(sacc[2*g0],   aH, &b0H[0]);
                mma16816(sacc[2*g0+1], aH, &b0H[2]);
                mma16816(sacc[2*g1],   aH, &b1H[0]);
                mma16816(sacc[2*g1+1], aH, &b1H[2]);
                mma16816(sacc[2*g0],   aH, &b0L[0]);
                mma16816(sacc[2*g0+1], aH, &b0L[2]);
                mma16816(sacc[2*g1],   aH, &b1L[0]);
                mma16816(sacc[2*g1+1], aH, &b1L[2]);
                mma16816(sacc[2*g0],   aL, &b0H[0]);
                mma16816(sacc[2*g0+1], aL, &b0H[2]);
                mma16816(sacc[2*g1],   aL, &b1H[0]);
                mma16816(sacc[2*g1+1], aL, &b1H[2]);
            }
        }

        // ---- exp, rowsum, attn write, P split -> smem ----
        #pragma unroll
        for (int na = 0; na < 16; na++) {
            float e[4];
            #pragma unroll
            for (int j = 0; j < 4; j++) {
                int col = kc*128 + na*8 + 2*(l & 3) + (j & 1);
                e[j] = (mskS[col] != 0.f) ? 0.f : __expf(sacc[na][j]*0.125f);
            }
            rs0 += e[0] + e[1];
            rs1 += e[2] + e[3];
            int c0 = kc*128 + na*8 + 2*(l & 3);
            if (attn_out) {
                *(float2*)&attn_out[abase + (long long)r0*SEQ + c0]
                    = make_float2(e[0], e[1]);
                *(float2*)&attn_out[abase + (long long)(r0 + 8)*SEQ + c0]
                    = make_float2(e[2], e[3]);
            }
            uint32_t h01, l01, h23, l23;
            split2(e[0], e[1], h01, l01);
            split2(e[2], e[3], h23, l23);
            int pc = na*8 + 2*(l & 3);
            *(uint32_t*)(cPH + r0*272 + pc*2)     = h01;
            *(uint32_t*)(cPL + r0*272 + pc*2)     = l01;
            *(uint32_t*)(cPH + (r0+8)*272 + pc*2) = h23;
            *(uint32_t*)(cPL + (r0+8)*272 + pc*2) = l23;
        }

        if (kc < 7) cp_wait<1>(); else cp_wait<0>();   // V ready
        __syncthreads();                                // V + P visible

        // ---- PV ----
        #pragma unroll
        for (int ks = 0; ks < 8; ks++) {
            uint32_t pH[4], pL[4];
            uint32_t poff = (uint32_t)(wid*16 + (l & 15))*272 + (ks*16 + (l >> 4)*8)*2;
            ldm4(pH, PH + poff); ldm4(pL, PL + poff);
            #pragma unroll
            for (int gp = 0; gp < 2; gp++) {
                int g0 = 2*gp, g1 = g0 + 1;
                uint32_t v0H[4], v0L[4], v1H[4], v1L[4];
                uint32_t vo0 = (uint32_t)(ks*16 + (l & 15))*144 + (g0*16 + ((l >> 4) << 3))*2;
                uint32_t vo1 = (uint32_t)(ks*16 + (l & 15))*144 + (g1*16 + ((l >> 4) << 3))*2;
                ldm4t(v0H, VH + vo0); ldm4t(v0L, VL + vo0);
                ldm4t(v1H, VH + vo1); ldm4t(v1L, VL + vo1);
                mma16816(cacc[2*g0],   pH, &v0H[0]);
                mma16816(cacc[2*g0+1], pH, &v0H[2]);
                mma16816(cacc[2*g1],   pH, &v1H[0]);
                mma16816(cacc[2*g1+1], pH, &v1H[2]);
                mma16816(cacc[2*g0],   pH, &v0L[0]);
                mma16816(cacc[2*g0+1], pH, &v0L[2]);
                mma16816(cacc[2*g1],   pH, &v1L[0]);
                mma16816(cacc[2*g1+1], pH, &v1L[2]);
                mma16816(cacc[2*g0],   pL, &v0H[0]);
                mma16816(cacc[2*g0+1], pL, &v0H[2]);
                mma16816(cacc[2*g1],   pL, &v1H[0]);
                mma16816(cacc[2*g1+1], pL, &v1H[2]);
            }
        }

        cp_wait<0>();      // K(kc+1) complete
        __syncthreads();
    }

    rs0 += __shfl_xor_sync(0xffffffffu, rs0, 1);
    rs0 += __shfl_xor_sync(0xffffffffu, rs0, 2);
    rs1 += __shfl_xor_sync(0xffffffffu, rs1, 1);
    rs1 += __shfl_xor_sync(0xffffffffu, rs1, 2);
    float inv0 = 1.f / rs0, inv1 = 1.f / rs1;
    if ((l & 3) == 0) {
        size_t rb = ((size_t)(layer*BATCH + b)*NHEADS + h)*SEQ + q0;
        rinv_g[rb + r0]     = inv0;
        rinv_g[rb + r0 + 8] = inv1;
    }
    #pragma unroll
    for (int na = 0; na < 8; na++) {
        int d = na*8 + 2*(l & 3);
        size_t o = ((size_t)(b*SEQ + q0 + r0))*DMODEL + h*DK + d;
        uint32_t h0, l0, h1, l1;
        split2(cacc[na][0]*inv0, cacc[na][1]*inv0, h0, l0);
        split2(cacc[na][2]*inv1, cacc[na][3]*inv1, h1, l1);
        *(uint32_t*)&g_ch[o]            = h0;
        *(uint32_t*)&g_cl[o]            = l0;
        *(uint32_t*)&g_ch[o + 8*DMODEL] = h1;
        *(uint32_t*)&g_cl[o + 8*DMODEL] = l1;
    }

    // ---- tail: normalize layer-1's attn block (same b,h,qb) ----
    if (attn_out && layer > 0) {
        long long pbase = abase - ALSTRIDE;
        const float* rsrc = rinv_g
            + ((size_t)((layer-1)*BATCH + b)*NHEADS + h)*SEQ + q0;
        for (int rr = wid; rr < 128; rr += 8) {
            float inv = rsrc[rr];
            float4* rowp = (float4*)(attn_out + pbase + (long long)rr*SEQ);
            #pragma unroll
            for (int i = 0; i < 8; i++) {
                float4 v = rowp[l + i*32];
                v.x *= inv; v.y *= inv; v.z *= inv; v.w *= inv;
                rowp[l + i*32] = v;
            }
        }
    }
}

// ---------------- normalize one layer's attention in place ----------------------
__global__ void attn_scale_kernel(float* __restrict__ attn,
                                  const float* __restrict__ rinv) {
    size_t i4 = ((size_t)blockIdx.x*256 + threadIdx.x) * 4;
    float inv = __ldg(&rinv[i4 >> 10]);
    float4 v = *(float4*)&attn[i4];
    v.x *= inv; v.y *= inv; v.z *= inv; v.w *= inv;
    *(float4*)&attn[i4] = v;
}

// ---------------- x = LayerNorm(y + x), writes x fp32 + hi/lo -------------------
__global__ __launch_bounds__(128) void add_ln_kernel(
        const float* __restrict__ y, float* __restrict__ x,
        __nv_bfloat16* __restrict__ xh, __nv_bfloat16* __restrict__ xl) {
    int row = blockIdx.x;
    int t   = threadIdx.x;
    const float* yr = y + (size_t)row*DMODEL;
    float*       xr = x + (size_t)row*DMODEL;
    float4 a = *(const float4*)&xr[t*4];
    float4 c = *(const float4*)&yr[t*4];
    float v[4] = {a.x + c.x, a.y + c.y, a.z + c.z, a.w + c.w};
    float s = v[0]+v[1]+v[2]+v[3];
    float s2 = v[0]*v[0]+v[1]*v[1]+v[2]*v[2]+v[3]*v[3];
    #pragma unroll
    for (int o = 16; o; o >>= 1) {
        s  += __shfl_xor_sync(0xffffffffu, s,  o);
        s2 += __shfl_xor_sync(0xffffffffu, s2, o);
    }
    __shared__ float sh[8];
    int w = t >> 5;
    if ((t & 31) == 0) { sh[w] = s; sh[4 + w] = s2; }
    __syncthreads();
    s  = sh[0] + sh[1] + sh[2] + sh[3];
    s2 = sh[4] + sh[5] + sh[6] + sh[7];
    float mean = s * (1.f/DMODEL);
    float var  = s2 * (1.f/DMODEL) - mean*mean;
    float invs = rsqrtf(var + 1e-5f);
    float o0 = (v[0]-mean)*invs, o1 = (v[1]-mean)*invs;
    float o2 = (v[2]-mean)*invs, o3 = (v[3]-mean)*invs;
    *(float4*)&xr[t*4] = make_float4(o0, o1, o2, o3);
    uint32_t h0, l0, h1, l1;
    split2(o0, o1, h0, l0); split2(o2, o3, h1, l1);
    size_t ob = (size_t)row*DMODEL + t*4;
    *(uint32_t*)&xh[ob]     = h0;  *(uint32_t*)&xl[ob]     = l0;
    *(uint32_t*)&xh[ob + 2] = h1;  *(uint32_t*)&xl[ob + 2] = l1;
}

__global__ void copy_x_kernel(float* __restrict__ out) {
    int i = blockIdx.x*256 + threadIdx.x;
    if (i < MROWS*DMODEL) out[i] = g_x[i];
}

// ---------------- driver ---------------------------------------------------------
extern "C" void kernel_launch(void* const* d_in, const int* in_sizes, int n_in,
                              void* d_out, int out_size) {
    const int*   tok = (const int*)  d_in[0];
    const float* emb = (const float*)d_in[1];
    const float* Wq  = (const float*)d_in[2];
    const float* Wk  = (const float*)d_in[3];
    const float* Wv  = (const float*)d_in[4];
    const float* Wo  = (const float*)d_in[5];
    const float* W1  = (const float*)d_in[6];
    const float* W2  = (const float*)d_in[7];
    float* out = (float*)d_out;

    float* attn_base = out + MROWS*DMODEL;
    bool   write_x   = true;
    if (out_size == MROWS*DMODEL)   { attn_base = nullptr; }
    else if (out_size == 201326592) { attn_base = out; write_x = false; }

    float *px, *py, *prinv;
    cudaGetSymbolAddress((void**)&px, g_x);
    cudaGetSymbolAddress((void**)&py, g_y);
    cudaGetSymbolAddress((void**)&prinv, g_rinv);
    __nv_bfloat16 *xh, *xl, *qh, *ql, *ch, *cl, *fh, *fl, *whi, *wlo;
    cudaGetSymbolAddress((void**)&xh, g_xh);
    cudaGetSymbolAddress((void**)&xl, g_xl);
    cudaGetSymbolAddress((void**)&qh, g_qh);
    cudaGetSymbolAddress((void**)&ql, g_ql);
    cudaGetSymbolAddress((void**)&ch, g_ch);
    cudaGetSymbolAddress((void**)&cl, g_cl);
    cudaGetSymbolAddress((void**)&fh, g_fh);
    cudaGetSymbolAddress((void**)&fl, g_fl);
    cudaGetSymbolAddress((void**)&whi, g_whi);
    cudaGetSymbolAddress((void**)&wlo, g_wlo);

    cudaFuncSetAttribute(attn_kernel, cudaFuncAttributeMaxDynamicSharedMemorySize, ATTN_SMEM);
    cudaFuncSetAttribute(mma_gemm<0>, cudaFuncAttributeMaxDynamicSharedMemorySize, GEMM_SMEM);
    cudaFuncSetAttribute(mma_gemm<1>, cudaFuncAttributeMaxDynamicSharedMemorySize, GEMM_SMEM);
    cudaFuncSetAttribute(mma_gemm<2>, cudaFuncAttributeMaxDynamicSharedMemorySize, GEMM_SMEM);

    // launch order: embed(1), wconv4(2), wconvW1(3), wconvW2(4) -> launch 5 = QKV gemm
    embed_kernel<<<(MROWS*DMODEL/2 + 255)/256, 256>>>(tok, emb);
    {
        dim3 g4(16, 16, 4*NLAYERS);
        wconv4_kernel<<<g4, 256>>>(Wq, Wk, Wv, Wo, whi, wlo);
        dim3 g1(64, 16, NLAYERS);
        wconv_kernel<<<g1, 256>>>(W1, whi + WOFF_1, wlo + WOFF_1, 512, 2048,
                                  (long)DMODEL*DFFN, (long)WL_STRIDE);
        dim3 g2(16, 64, NLAYERS);
        wconv_kernel<<<g2, 256>>>(W2, whi + WOFF_2, wlo + WOFF_2, 2048, 512,
                                  (long)DFFN*DMODEL, (long)WL_STRIDE);
    }

    dim3 gQKV(12, 32);    // N=1536
    dim3 gO(4, 32);       // N=512
    dim3 gF1(16, 32);     // N=2048
    dim3 gAttn(SEQ/128, NHEADS, BATCH);

    for (int l = 0; l < NLAYERS; l++) {
        const __nv_bfloat16* wh = whi + (size_t)l*WL_STRIDE;
        const __nv_bfloat16* wl = wlo + (size_t)l*WL_STRIDE;

        mma_gemm<1><<<gQKV, 256, GEMM_SMEM>>>(xh, xl, wh + WOFF_QKV, wl + WOFF_QKV,
                                              nullptr, qh, ql, 1536, 512);
        attn_kernel<<<gAttn, 256, ATTN_SMEM>>>(tok, attn_base, prinv, l);
        mma_gemm<0><<<gO, 256, GEMM_SMEM>>>(ch, cl, wh + WOFF_O, wl + WOFF_O,
                                            py, nullptr, nullptr, 512, 512);
        add_ln_kernel<<<MROWS, 128>>>(py, px, xh, xl);
        mma_gemm<2><<<gF1, 256, GEMM_SMEM>>>(xh, xl, wh + WOFF_1, wl + WOFF_1,
                                             nullptr, fh, fl, 2048, 512);
        mma_gemm<0><<<gO, 256, GEMM_SMEM>>>(fh, fl, wh + WOFF_2, wl + WOFF_2,
                                            py, nullptr, nullptr, 512, 2048);
        add_ln_kernel<<<MROWS, 128>>>(py, px, xh, xl);
    }

    if (attn_base) {
        // only the final layer still needs normalization (layers 0..4 were
        // normalized by the fused tail in attn_kernel of the following layer)
        const long long last = (long long)(NLAYERS-1)*ALSTRIDE;
        attn_scale_kernel<<<(unsigned)(ALSTRIDE/1024), 256>>>(
            attn_base + last, prinv + (size_t)(NLAYERS-1)*BATCH*NHEADS*SEQ);
    }
    if (write_x)
        copy_x_kernel<<<(MROWS*DMODEL + 255)/256, 256>>>(out);
}

// round 8
// speedup vs baseline: 1.0123x; 1.0123x over previous
#include <cuda_runtime.h>
#include <cuda_bf16.h>
#include <cstdint>

#define BATCH   4
#define SEQ     1024
#define DMODEL  512
#define NHEADS  8
#define DK      64
#define NLAYERS 6
#define DFFN    2048
#define MROWS   (BATCH*SEQ)   // 4096
#define ALSTRIDE ((long long)BATCH*NHEADS*SEQ*SEQ)   // attn layer stride

// ---------------- scratch (device globals) -------------------------------------
__device__ float g_x  [MROWS*DMODEL];     // residual stream (fp32)
__device__ float g_y  [MROWS*DMODEL];     // gemm fp32 out (pre-LN)
__device__ float g_rinv[NLAYERS*BATCH*NHEADS*SEQ];                    // 1/rowsum
__device__ __nv_bfloat16 g_xh[MROWS*DMODEL],  g_xl[MROWS*DMODEL];    // x split
__device__ __nv_bfloat16 g_qh[3*MROWS*DMODEL], g_ql[3*MROWS*DMODEL]; // q|k|v split
__device__ __nv_bfloat16 g_ch[MROWS*DMODEL],  g_cl[MROWS*DMODEL];    // ctx split
__device__ __nv_bfloat16 g_fh[MROWS*DFFN],    g_fl[MROWS*DFFN];      // ffn split

// bf16 split transposed weights Wt[n][k]: qkv(1536x512)|o(512x512)|w1(2048x512)|w2(512x2048)
#define WL_STRIDE 3145728
#define WOFF_QKV  0
#define WOFF_O    786432
#define WOFF_1    1048576
#define WOFF_2    2097152
__device__ __nv_bfloat16 g_whi[NLAYERS*WL_STRIDE];
__device__ __nv_bfloat16 g_wlo[NLAYERS*WL_STRIDE];

// ---------------- helpers -------------------------------------------------------
__device__ __forceinline__ uint32_t smem_u32(const void* p) {
    uint32_t a;
    asm("{ .reg .u64 t; cvta.to.shared.u64 t, %1; cvt.u32.u64 %0, t; }" : "=r"(a) : "l"(p));
    return a;
}
__device__ __forceinline__ void ldm4(uint32_t* r, uint32_t a) {
    asm volatile("ldmatrix.sync.aligned.m8n8.x4.shared.b16 {%0,%1,%2,%3}, [%4];"
        : "=r"(r[0]), "=r"(r[1]), "=r"(r[2]), "=r"(r[3]) : "r"(a));
}
__device__ __forceinline__ void ldm4t(uint32_t* r, uint32_t a) {
    asm volatile("ldmatrix.sync.aligned.m8n8.x4.trans.shared.b16 {%0,%1,%2,%3}, [%4];"
        : "=r"(r[0]), "=r"(r[1]), "=r"(r[2]), "=r"(r[3]) : "r"(a));
}
__device__ __forceinline__ void mma16816(float* d, const uint32_t* a, const uint32_t* b) {
    asm volatile("mma.sync.aligned.m16n8k16.row.col.f32.bf16.bf16.f32 "
        "{%0,%1,%2,%3}, {%4,%5,%6,%7}, {%8,%9}, {%0,%1,%2,%3};"
        : "+f"(d[0]), "+f"(d[1]), "+f"(d[2]), "+f"(d[3])
        : "r"(a[0]), "r"(a[1]), "r"(a[2]), "r"(a[3]), "r"(b[0]), "r"(b[1]));
}
__device__ __forceinline__ void split2(float x, float y, uint32_t& hi, uint32_t& lo) {
    __nv_bfloat162 h = __floats2bfloat162_rn(x, y);
    float hx = __bfloat162float(h.x), hy = __bfloat162float(h.y);
    __nv_bfloat162 l2 = __floats2bfloat162_rn(x - hx, y - hy);
    hi = *(uint32_t*)&h;
    lo = *(uint32_t*)&l2;
}
__device__ __forceinline__ void cpa16(uint32_t dst, const void* src) {
    asm volatile("cp.async.cg.shared.global [%0], [%1], 16;" :: "r"(dst), "l"(src));
}
#define CP_COMMIT() asm volatile("cp.async.commit_group;" ::: "memory")
template<int N> __device__ __forceinline__ void cp_wait() {
    asm volatile("cp.async.wait_group %0;" :: "n"(N) : "memory");
}

// ---------------- embedding + positional encoding (writes x + split) -----------
__global__ void embed_kernel(const int* __restrict__ tok,
                             const float* __restrict__ emb) {
    int p = blockIdx.x * 256 + threadIdx.x;
    if (p >= MROWS*DMODEL/2) return;
    int idx = p * 2;
    int row = idx >> 9;
    int d   = idx & (DMODEL-1);
    int s   = row & (SEQ-1);
    int tk  = tok[row];
    float freq = expf((float)d * (-9.210340371976184f / (float)DMODEL));
    float ang  = (float)s * freq;
    float v0 = emb[tk*DMODEL + d]     + sinf(ang);
    float v1 = emb[tk*DMODEL + d + 1] + cosf(ang);
    *(float2*)&g_x[idx] = make_float2(v0, v1);
    uint32_t h, l; split2(v0, v1, h, l);
    *(uint32_t*)&g_xh[idx] = h;
    *(uint32_t*)&g_xl[idx] = l;
}

// ---------------- weight transpose + split kernels ------------------------------
__global__ void wconv4_kernel(const float* __restrict__ Wq, const float* __restrict__ Wk,
                              const float* __restrict__ Wv, const float* __restrict__ Wo,
                              __nv_bfloat16* __restrict__ hi, __nv_bfloat16* __restrict__ lo) {
    __shared__ float tl[32][33];
    int z = blockIdx.z, lyr = z >> 2, which = z & 3;
    const float* src;
    size_t doff;
    switch (which) {
        case 0: src = Wq; doff = WOFF_QKV;          break;
        case 1: src = Wk; doff = WOFF_QKV + 262144; break;
        case 2: src = Wv; doff = WOFF_QKV + 524288; break;
        default: src = Wo; doff = WOFF_O;           break;
    }
    src += (size_t)lyr * 262144;
    hi  += (size_t)lyr * WL_STRIDE + doff;
    lo  += (size_t)lyr * WL_STRIDE + doff;
    int n0 = blockIdx.x*32, k0 = blockIdx.y*32;
    int tx = threadIdx.x & 31, tg = threadIdx.x >> 5;
    #pragma unroll
    for (int r = tg; r < 32; r += 8)
        tl[r][tx] = src[(size_t)(k0 + r)*512 + n0 + tx];
    __syncthreads();
    #pragma unroll
    for (int r = tg; r < 32; r += 8) {
        float x = tl[tx][r];
        __nv_bfloat16 h = __float2bfloat16(x);
        size_t o = (size_t)(n0 + r)*512 + k0 + tx;
        hi[o] = h;
        lo[o] = __float2bfloat16(x - __bfloat162float(h));
    }
}

__global__ void wconv_kernel(const float* __restrict__ src,
                             __nv_bfloat16* __restrict__ hi,
                             __nv_bfloat16* __restrict__ lo,
                             int K, int N, long srcStride, long dstStride) {
    __shared__ float tl[32][33];
    int l = blockIdx.z;
    src += (size_t)l * srcStride;
    hi  += (size_t)l * dstStride;
    lo  += (size_t)l * dstStride;
    int n0 = blockIdx.x*32, k0 = blockIdx.y*32;
    int tx = threadIdx.x & 31, tg = threadIdx.x >> 5;
    #pragma unroll
    for (int r = tg; r < 32; r += 8)
        tl[r][tx] = src[(size_t)(k0 + r)*N + n0 + tx];
    __syncthreads();
    #pragma unroll
    for (int r = tg; r < 32; r += 8) {
        float x = tl[tx][r];
        __nv_bfloat16 h = __float2bfloat16(x);
        size_t o = (size_t)(n0 + r)*K + k0 + tx;
        hi[o] = h;
        lo[o] = __float2bfloat16(x - __bfloat162float(h));
    }
}

// ---------------- 3-stage pipelined HMMA GEMM: C = A @ Bt^T ---------------------
#define GSTAGE    73728
#define GEMM_SMEM (3*GSTAGE)

__device__ __forceinline__ void gemm_stage_load(
        uint32_t sbase, int t,
        const __nv_bfloat16* Ah, const __nv_bfloat16* Al,
        const __nv_bfloat16* Bh, const __nv_bfloat16* Bl,
        int m0, int n0, int k0, int K) {
    #pragma unroll
    for (int i = 0; i < 4; i++) {
        int seg = i*256 + t;
        int r = seg >> 3, c = seg & 7;
        uint32_t so = (uint32_t)r*144 + c*16;
        size_t ga = (size_t)(m0 + r)*K + k0 + c*8;
        size_t gb = (size_t)(n0 + r)*K + k0 + c*8;
        cpa16(sbase +         so, Ah + ga);
        cpa16(sbase + 18432 + so, Al + ga);
        cpa16(sbase + 36864 + so, Bh + gb);
        cpa16(sbase + 55296 + so, Bl + gb);
    }
}

template<int MODE>
__global__ __launch_bounds__(256) void mma_gemm(
        const __nv_bfloat16* __restrict__ Ah, const __nv_bfloat16* __restrict__ Al,
        const __nv_bfloat16* __restrict__ Bh, const __nv_bfloat16* __restrict__ Bl,
        float* __restrict__ Cf,
        __nv_bfloat16* __restrict__ Ch, __nv_bfloat16* __restrict__ Cl,
        int N, int K) {
    extern __shared__ char sm[];
    const uint32_t sb = smem_u32(sm);
    int t = threadIdx.x, l = t & 31, wid = t >> 5;
    int m0 = blockIdx.y * 128, n0 = blockIdx.x * 128;
    int wm = (wid & 3) * 32, wn = (wid >> 2) * 64;

    float acc[2][8][4];
    #pragma unroll
    for (int i = 0; i < 2; i++)
        #pragma unroll
        for (int j = 0; j < 8; j++)
            #pragma unroll
            for (int q = 0; q < 4; q++) acc[i][j][q] = 0.f;

    const int NK = K >> 6;
    gemm_stage_load(sb, t, Ah, Al, Bh, Bl, m0, n0, 0, K);
    CP_COMMIT();
    if (NK > 1) {
        gemm_stage_load(sb + GSTAGE, t, Ah, Al, Bh, Bl, m0, n0, 64, K);
        CP_COMMIT();
    }

    int s_cur = 0, s_pre = 2;
    for (int kc = 0; kc < NK; kc++) {
        if (kc < NK - 1) cp_wait<1>(); else cp_wait<0>();
        __syncthreads();
        if (kc + 2 < NK) {
            gemm_stage_load(sb + s_pre*GSTAGE, t, Ah, Al, Bh, Bl,
                            m0, n0, (kc+2)*64, K);
            CP_COMMIT();
        }

        const uint32_t SB = sb + s_cur*GSTAGE;
        const uint32_t AH = SB, AL = SB + 18432, BH = SB + 36864, BL = SB + 55296;
        #pragma unroll
        for (int ks = 0; ks < 4; ks++) {
            uint32_t aH[2][4], aL[2][4];
            #pragma unroll
            for (int ra = 0; ra < 2; ra++) {
                uint32_t off = (uint32_t)(wm + ra*16 + (l & 15))*144 + (ks*16 + (l >> 4)*8)*2;
                ldm4(aH[ra], AH + off);
                ldm4(aL[ra], AL + off);
            }
            #pragma unroll
            for (int g = 0; g < 4; g++) {
                uint32_t bH[4], bL[4];
                uint32_t off = (uint32_t)(wn + g*16 + (l & 7) + ((l >> 4) << 3))*144
                             + (ks*16 + ((l >> 3) & 1)*8)*2;
                ldm4(bH, BH + off); ldm4(bL, BL + off);
                mma16816(acc[0][2*g],   aH[0], &bH[0]);
                mma16816(acc[0][2*g+1], aH[0], &bH[2]);
                mma16816(acc[1][2*g],   aH[1], &bH[0]);
                mma16816(acc[1][2*g+1], aH[1], &bH[2]);
                mma16816(acc[0][2*g],   aH[0], &bL[0]);
                mma16816(acc[0][2*g+1], aH[0], &bL[2]);
                mma16816(acc[1][2*g],   aH[1], &bL[0]);
                mma16816(acc[1][2*g+1], aH[1], &bL[2]);
                mma16816(acc[0][2*g],   aL[0], &bH[0]);
                mma16816(acc[0][2*g+1], aL[0], &bH[2]);
                mma16816(acc[1][2*g],   aL[1], &bH[0]);
                mma16816(acc[1][2*g+1], aL[1], &bH[2]);
            }
        }
        s_cur = (s_cur == 2) ? 0 : s_cur + 1;
        s_pre = (s_pre == 2) ? 0 : s_pre + 1;
    }

    #pragma unroll
    for (int ra = 0; ra < 2; ra++)
        #pragma unroll
        for (int na = 0; na < 8; na++) {
            int n = n0 + wn + na*8 + 2*(l & 3);
            #pragma unroll
            for (int half = 0; half < 2; half++) {
                int m = m0 + wm + ra*16 + (l >> 2) + half*8;
                float2 v = make_float2(acc[ra][na][half*2], acc[ra][na][half*2 + 1]);
                if (MODE == 0) {
                    *(float2*)&Cf[(size_t)m*N + n] = v;
                } else {
                    if (MODE == 2) { v.x = fmaxf(v.x, 0.f); v.y = fmaxf(v.y, 0.f); }
                    uint32_t hh, ll; split2(v.x, v.y, hh, ll);
                    size_t off;
                    if (MODE == 1) {
                        int sel = n >> 9, n2 = n & 511;
                        int h = n2 >> 6, dk = n2 & 63;
                        int b = m >> 10, s = m & 1023;
                        off = (size_t)sel*MROWS*DMODEL
                            + ((size_t)((b*NHEADS + h)*SEQ + s))*DK + dk;
                    } else {
                        off = (size_t)m*N + n;
                    }
                    *(uint32_t*)&Ch[off] = hh;
                    *(uint32_t*)&Cl[off] = ll;
                }
            }
        }
}

// ---------------- single-pass HMMA attention, K double-buffered ------------------
#define ATTN_SMEM 221184

__global__ __launch_bounds__(256) void attn_kernel(
        const int* __restrict__ tok, float* __restrict__ attn_out,
        float* __restrict__ rinv_g, int layer) {
    extern __shared__ char sm[];
    const uint32_t sb = smem_u32(sm);
    const uint32_t QH = sb,           QL = sb + 18432;
    const uint32_t VH = sb + 110592,  VL = sb + 129024;
    const uint32_t PH = sb + 147456,  PL = sb + 182272;
    char* cPH = sm + 147456;  char* cPL = sm + 182272;
    float* mskS = (float*)(sm + 217088);   // 1024 floats

    int t = threadIdx.x, l = t & 31, wid = t >> 5;
    int qb = blockIdx.x, h = blockIdx.y, b = blockIdx.z;
    int q0 = qb * 128;
    size_t hoff = ((size_t)(b*NHEADS + h)*SEQ)*DK;
    const __nv_bfloat16* qh = g_qh + hoff + (size_t)q0*DK;
    const __nv_bfloat16* ql = g_ql + hoff + (size_t)q0*DK;
    const __nv_bfloat16* kh = g_qh + (size_t)MROWS*DMODEL + hoff;
    const __nv_bfloat16* kl = g_ql + (size_t)MROWS*DMODEL + hoff;
    const __nv_bfloat16* vh = kh + (size_t)MROWS*DMODEL;
    const __nv_bfloat16* vl = kl + (size_t)MROWS*DMODEL;

    for (int j = t; j < SEQ; j += 256)
        mskS[j] = (tok[b*SEQ + j] == 0) ? 1.f : 0.f;
    #pragma unroll
    for (int i = 0; i < 4; i++) {                 // Q + K(0) prologue
        int seg = i*256 + t, r = seg >> 3, c = seg & 7;
        uint32_t so = (uint32_t)r*144 + c*16;
        cpa16(QH + so, qh + (size_t)r*64 + c*8);
        cpa16(QL + so, ql + (size_t)r*64 + c*8);
        cpa16(sb + 36864 + so, kh + (size_t)r*64 + c*8);
        cpa16(sb + 55296 + so, kl + (size_t)r*64 + c*8);
    }
    CP_COMMIT(); cp_wait<0>();
    __syncthreads();

    float rs0 = 0.f, rs1 = 0.f;
    float cacc[8][4];
    #pragma unroll
    for (int j = 0; j < 8; j++)
        #pragma unroll
        for (int q = 0; q < 4; q++) cacc[j][q] = 0.f;

    int r0 = wid*16 + (l >> 2);
    long long abase = ((((long long)layer*BATCH + b)*NHEADS + h)*SEQ + q0)
                      * (long long)SEQ;

    for (int kc = 0; kc < 8; kc++) {
        const uint32_t KHc = sb + 36864 + (uint32_t)(kc & 1)*36864;
        const uint32_t KLc = KHc + 18432;
        #pragma unroll
        for (int i = 0; i < 4; i++) {
            int seg = i*256 + t, r = seg >> 3, c = seg & 7;
            uint32_t so = (uint32_t)r*144 + c*16;
            cpa16(VH + so, vh + (size_t)(kc*128 + r)*64 + c*8);
            cpa16(VL + so, vl + (size_t)(kc*128 + r)*64 + c*8);
        }
        CP_COMMIT();
        if (kc < 7) {
            const uint32_t KHn = sb + 36864 + (uint32_t)((kc+1) & 1)*36864;
            #pragma unroll
            for (int i = 0; i < 4; i++) {
                int seg = i*256 + t, r = seg >> 3, c = seg & 7;
                uint32_t so = (uint32_t)r*144 + c*16;
                cpa16(KHn + so,         kh + (size_t)((kc+1)*128 + r)*64 + c*8);
                cpa16(KHn + 18432 + so, kl + (size_t)((kc+1)*128 + r)*64 + c*8);
            }
            CP_COMMIT();
        }

        // ---- QK on resident K(kc) ----
        float sacc[16][4];
        #pragma unroll
        for (int j = 0; j < 16; j++)
            #pragma unroll
            for (int q = 0; q < 4; q++) sacc[j][q] = 0.f;

        #pragma unroll
        for (int ks = 0; ks < 4; ks++) {
            uint32_t aH[4], aL[4];
            uint32_t aoff = (uint32_t)(wid*16 + (l & 15))*144 + (ks*16 + (l >> 4)*8)*2;
            ldm4(aH, QH + aoff); ldm4(aL, QL + aoff);
            #pragma unroll
            for (int gp = 0; gp < 4; gp++) {
                int g0 = 2*gp, g1 = g0 + 1;
                uint32_t b0H[4], b0L[4], b1H[4], b1L[4];
                uint32_t bo0 = (uint32_t)(g0*16 + (l & 7) + ((l >> 4) << 3))*144
                             + (ks*16 + ((l >> 3) & 1)*8)*2;
                uint32_t bo1 = (uint32_t)(g1*16 + (l & 7) + ((l >> 4) << 3))*144
                             + (ks*16 + ((l >> 3) & 1)*8)*2;
                ldm4(b0H, KHc + bo0); ldm4(b0L, KLc + bo0);
                ldm4(b1H, KHc + bo1); ldm4(b1L, KLc + bo1);
                mma16816(sacc[2*g0],   aH, &b0H[0]);
                mma16816(sacc[2*g0+1], aH, &b0H[2]);
                mma16816(sacc[2*g1],   aH, &b1H[0]);
                mma16816(sacc[2*g1+1], aH, &b1H[2]);
                mma16816(sacc[2*g0],   aH, &b0L[0]);
                mma16816(sacc[2*g0+1], aH, &b0L[2]);
                mma16816(sacc[2*g1],   aH, &b1L[0]);
                mma16816(sacc[2*g1+1], aH, &b1L[2]);
                mma16816(sacc[2*g0],   aL, &b0H[0]);
                mma16816(sacc[2*g0+1], aL, &b0H[2]);
                mma16816(sacc[2*g1],   aL, &b1H[0]);
                mma16816(sacc[2*g1+1], aL, &b1H[2]);
            }
        }

        // ---- exp, rowsum, attn write, P split -> smem ----
        #pragma unroll
        for (int na = 0; na < 16; na++) {
            float e[4];
            #pragma unroll
            for (int j = 0; j < 4; j++) {
                int col = kc*128 + na*8 + 2*(l & 3) + (j & 1);
                e[j] = (mskS[col] != 0.f) ? 0.f : __expf(sacc[na][j]*0.125f);
            }
            rs0 += e[0] + e[1];
            rs1 += e[2] + e[3];
            int c0 = kc*128 + na*8 + 2*(l & 3);
            if (attn_out) {
                *(float2*)&attn_out[abase + (long long)r0*SEQ + c0]
                    = make_float2(e[0], e[1]);
                *(float2*)&attn_out[abase + (long long)(r0 + 8)*SEQ + c0]
                    = make_float2(e[2], e[3]);
            }
            uint32_t h01, l01, h23, l23;
            split2(e[0], e[1], h01, l01);
            split2(e[2], e[3], h23, l23);
            int pc = na*8 + 2*(l & 3);
            *(uint32_t*)(cPH + r0*272 + pc*2)     = h01;
            *(uint32_t*)(cPL + r0*272 + pc*2)     = l01;
            *(uint32_t*)(cPH + (r0+8)*272 + pc*2) = h23;
            *(uint32_t*)(cPL + (r0+8)*272 + pc*2) = l23;
        }

        if (kc < 7) cp_wait<1>(); else cp_wait<0>();   // V ready
        __syncthreads();                                // V + P visible

        // ---- PV ----
        #pragma unroll
        for (int ks = 0; ks < 8; ks++) {
            uint32_t pH[4], pL[4];
            uint32_t poff = (uint32_t)(wid*16 + (l & 15))*272 + (ks*16 + (l >> 4)*8)*2;
            ldm4(pH, PH + poff); ldm4(pL, PL + poff);
            #pragma unroll
            for (int gp = 0; gp < 2; gp++) {
                int g0 = 2*gp, g1 = g0 + 1;
                uint32_t v0H[4], v0L[4], v1H[4], v1L[4];
                uint32_t vo0 = (uint32_t)(ks*16 + (l & 15))*144 + (g0*16 + ((l >> 4) << 3))*2;
                uint32_t vo1 = (uint32_t)(ks*16 + (l & 15))*144 + (g1*16 + ((l >> 4) << 3))*2;
                ldm4t(v0H, VH + vo0); ldm4t(v0L, VL + vo0);
                ldm4t(v1H, VH + vo1); ldm4t(v1L, VL + vo1);
                mma16816(cacc[2*g0],   pH, &v0H[0]);
                mma16816(cacc[2*g0+1], pH, &v0H[2]);
                mma16816(cacc[2*g1],   pH, &v1H[0]);
                mma16816(cacc[2*g1+1], pH, &v1H[2]);
                mma16816(cacc[2*g0],   pH, &v0L[0]);
                mma16816(cacc[2*g0+1], pH, &v0L[2]);
                mma16816(cacc[2*g1],   pH, &v1L[0]);
                mma16816(cacc[2*g1+1], pH, &v1L[2]);
                mma16816(cacc[2*g0],   pL, &v0H[0]);
                mma16816(cacc[2*g0+1], pL, &v0H[2]);
                mma16816(cacc[2*g1],   pL, &v1H[0]);
                mma16816(cacc[2*g1+1], pL, &v1H[2]);
            }
        }

        cp_wait<0>();      // K(kc+1) complete
        __syncthreads();
    }

    rs0 += __shfl_xor_sync(0xffffffffu, rs0, 1);
    rs0 += __shfl_xor_sync(0xffffffffu, rs0, 2);
    rs1 += __shfl_xor_sync(0xffffffffu, rs1, 1);
    rs1 += __shfl_xor_sync(0xffffffffu, rs1, 2);
    float inv0 = 1.f / rs0, inv1 = 1.f / rs1;
    if ((l & 3) == 0) {
        size_t rb = ((size_t)(layer*BATCH + b)*NHEADS + h)*SEQ + q0;
        rinv_g[rb + r0]     = inv0;
        rinv_g[rb + r0 + 8] = inv1;
    }
    #pragma unroll
    for (int na = 0; na < 8; na++) {
        int d = na*8 + 2*(l & 3);
        size_t o = ((size_t)(b*SEQ + q0 + r0))*DMODEL + h*DK + d;
        uint32_t h0, l0, h1, l1;
        split2(cacc[na][0]*inv0, cacc[na][1]*inv0, h0, l0);
        split2(cacc[na][2]*inv1, cacc[na][3]*inv1, h1, l1);
        *(uint32_t*)&g_ch[o]            = h0;
        *(uint32_t*)&g_cl[o]            = l0;
        *(uint32_t*)&g_ch[o + 8*DMODEL] = h1;
        *(uint32_t*)&g_cl[o + 8*DMODEL] = l1;
    }
}

// ---------------- normalize one layer's attention in place ----------------------
__global__ void attn_scale_kernel(float* __restrict__ attn,
                                  const float* __restrict__ rinv) {
    size_t i4 = ((size_t)blockIdx.x*256 + threadIdx.x) * 4;
    float inv = __ldg(&rinv[i4 >> 10]);
    float4 v = *(float4*)&attn[i4];
    v.x *= inv; v.y *= inv; v.z *= inv; v.w *= inv;
    *(float4*)&attn[i4] = v;
}

// ---------------- x = LayerNorm(y + x), writes x fp32 + hi/lo -------------------
__global__ __launch_bounds__(128) void add_ln_kernel(
        const float* __restrict__ y, float* __restrict__ x,
        __nv_bfloat16* __restrict__ xh, __nv_bfloat16* __restrict__ xl) {
    int row = blockIdx.x;
    int t   = threadIdx.x;
    const float* yr = y + (size_t)row*DMODEL;
    float*       xr = x + (size_t)row*DMODEL;
    float4 a = *(const float4*)&xr[t*4];
    float4 c = *(const float4*)&yr[t*4];
    float v[4] = {a.x + c.x, a.y + c.y, a.z + c.z, a.w + c.w};
    float s = v[0]+v[1]+v[2]+v[3];
    float s2 = v[0]*v[0]+v[1]*v[1]+v[2]*v[2]+v[3]*v[3];
    #pragma unroll
    for (int o = 16; o; o >>= 1) {
        s  += __shfl_xor_sync(0xffffffffu, s,  o);
        s2 += __shfl_xor_sync(0xffffffffu, s2, o);
    }
    __shared__ float sh[8];
    int w = t >> 5;
    if ((t & 31) == 0) { sh[w] = s; sh[4 + w] = s2; }
    __syncthreads();
    s  = sh[0] + sh[1] + sh[2] + sh[3];
    s2 = sh[4] + sh[5] + sh[6] + sh[7];
    float mean = s * (1.f/DMODEL);
    float var  = s2 * (1.f/DMODEL) - mean*mean;
    float invs = rsqrtf(var + 1e-5f);
    float o0 = (v[0]-mean)*invs, o1 = (v[1]-mean)*invs;
    float o2 = (v[2]-mean)*invs, o3 = (v[3]-mean)*invs;
    *(float4*)&xr[t*4] = make_float4(o0, o1, o2, o3);
    uint32_t h0, l0, h1, l1;
    split2(o0, o1, h0, l0); split2(o2, o3, h1, l1);
    size_t ob = (size_t)row*DMODEL + t*4;
    *(uint32_t*)&xh[ob]     = h0;  *(uint32_t*)&xl[ob]     = l0;
    *(uint32_t*)&xh[ob + 2] = h1;  *(uint32_t*)&xl[ob + 2] = l1;
}

__global__ void copy_x_kernel(float* __restrict__ out) {
    int i = blockIdx.x*256 + threadIdx.x;
    if (i < MROWS*DMODEL) out[i] = g_x[i];
}

// ---------------- driver ---------------------------------------------------------
extern "C" void kernel_launch(void* const* d_in, const int* in_sizes, int n_in,
                              void* d_out, int out_size) {
    const int*   tok = (const int*)  d_in[0];
    const float* emb = (const float*)d_in[1];
    const float* Wq  = (const float*)d_in[2];
    const float* Wk  = (const float*)d_in[3];
    const float* Wv  = (const float*)d_in[4];
    const float* Wo  = (const float*)d_in[5];
    const float* W1  = (const float*)d_in[6];
    const float* W2  = (const float*)d_in[7];
    float* out = (float*)d_out;

    float* attn_base = out + MROWS*DMODEL;
    bool   write_x   = true;
    if (out_size == MROWS*DMODEL)   { attn_base = nullptr; }
    else if (out_size == 201326592) { attn_base = out; write_x = false; }

    float *px, *py, *prinv;
    cudaGetSymbolAddress((void**)&px, g_x);
    cudaGetSymbolAddress((void**)&py, g_y);
    cudaGetSymbolAddress((void**)&prinv, g_rinv);
    __nv_bfloat16 *xh, *xl, *qh, *ql, *ch, *cl, *fh, *fl, *whi, *wlo;
    cudaGetSymbolAddress((void**)&xh, g_xh);
    cudaGetSymbolAddress((void**)&xl, g_xl);
    cudaGetSymbolAddress((void**)&qh, g_qh);
    cudaGetSymbolAddress((void**)&ql, g_ql);
    cudaGetSymbolAddress((void**)&ch, g_ch);
    cudaGetSymbolAddress((void**)&cl, g_cl);
    cudaGetSymbolAddress((void**)&fh, g_fh);
    cudaGetSymbolAddress((void**)&fl, g_fl);
    cudaGetSymbolAddress((void**)&whi, g_whi);
    cudaGetSymbolAddress((void**)&wlo, g_wlo);

    cudaFuncSetAttribute(attn_kernel, cudaFuncAttributeMaxDynamicSharedMemorySize, ATTN_SMEM);
    cudaFuncSetAttribute(mma_gemm<0>, cudaFuncAttributeMaxDynamicSharedMemorySize, GEMM_SMEM);
    cudaFuncSetAttribute(mma_gemm<1>, cudaFuncAttributeMaxDynamicSharedMemorySize, GEMM_SMEM);
    cudaFuncSetAttribute(mma_gemm<2>, cudaFuncAttributeMaxDynamicSharedMemorySize, GEMM_SMEM);

    // ---- side stream for attn normalization overlap (fresh per call; graph
    //      replays don't re-run host code). Fallback to main stream on error. ----
    cudaStream_t side = 0;
    cudaEvent_t evFork[NLAYERS], evJoin;
    bool useSide = attn_base != nullptr;
    if (useSide && cudaStreamCreateWithFlags(&side, cudaStreamNonBlocking) != cudaSuccess)
        useSide = false;
    if (useSide) {
        for (int l = 0; l < NLAYERS && useSide; l++)
            if (cudaEventCreateWithFlags(&evFork[l], cudaEventDisableTiming) != cudaSuccess)
                useSide = false;
        if (useSide && cudaEventCreateWithFlags(&evJoin, cudaEventDisableTiming) != cudaSuccess)
            useSide = false;
    }

    embed_kernel<<<(MROWS*DMODEL/2 + 255)/256, 256>>>(tok, emb);
    {
        dim3 g4(16, 16, 4*NLAYERS);
        wconv4_kernel<<<g4, 256>>>(Wq, Wk, Wv, Wo, whi, wlo);
        dim3 g1(64, 16, NLAYERS);
        wconv_kernel<<<g1, 256>>>(W1, whi + WOFF_1, wlo + WOFF_1, 512, 2048,
                                  (long)DMODEL*DFFN, (long)WL_STRIDE);
        dim3 g2(16, 64, NLAYERS);
        wconv_kernel<<<g2, 256>>>(W2, whi + WOFF_2, wlo + WOFF_2, 2048, 512,
                                  (long)DFFN*DMODEL, (long)WL_STRIDE);
    }

    dim3 gQKV(12, 32);    // N=1536
    dim3 gO(4, 32);       // N=512
    dim3 gF1(16, 32);     // N=2048
    dim3 gAttn(SEQ/128, NHEADS, BATCH);
    const unsigned gScale = (unsigned)(ALSTRIDE/1024);

    for (int l = 0; l < NLAYERS; l++) {
        const __nv_bfloat16* wh = whi + (size_t)l*WL_STRIDE;
        const __nv_bfloat16* wl = wlo + (size_t)l*WL_STRIDE;

        mma_gemm<1><<<gQKV, 256, GEMM_SMEM>>>(xh, xl, wh + WOFF_QKV, wl + WOFF_QKV,
                                              nullptr, qh, ql, 1536, 512);
        attn_kernel<<<gAttn, 256, ATTN_SMEM>>>(tok, attn_base, prinv, l);

        if (attn_base) {
            float* al = attn_base + (long long)l*ALSTRIDE;
            const float* rl = prinv + (size_t)l*BATCH*NHEADS*SEQ;
            if (useSide) {
                cudaEventRecord(evFork[l], 0);
                cudaStreamWaitEvent(side, evFork[l], 0);
                attn_scale_kernel<<<gScale, 256, 0, side>>>(al, rl);
            } else {
                attn_scale_kernel<<<gScale, 256>>>(al, rl);
            }
        }

        mma_gemm<0><<<gO, 256, GEMM_SMEM>>>(ch, cl, wh + WOFF_O, wl + WOFF_O,
                                            py, nullptr, nullptr, 512, 512);
        add_ln_kernel<<<MROWS, 128>>>(py, px, xh, xl);
        mma_gemm<2><<<gF1, 256, GEMM_SMEM>>>(xh, xl, wh + WOFF_1, wl + WOFF_1,
                                             nullptr, fh, fl, 2048, 512);
        mma_gemm<0><<<gO, 256, GEMM_SMEM>>>(fh, fl, wh + WOFF_2, wl + WOFF_2,
                                            py, nullptr, nullptr, 512, 2048);
        add_ln_kernel<<<MROWS, 128>>>(py, px, xh, xl);
    }

    if (useSide) {          // join side stream back into the captured main stream
        cudaEventRecord(evJoin, side);
        cudaStreamWaitEvent(0, evJoin, 0);
    }

    if (write_x)
        copy_x_kernel<<<(MROWS*DMODEL + 255)/256, 256>>>(out);
}